// round 4
// baseline (speedup 1.0000x reference)
#include <cuda_runtime.h>
#include <cuda_bf16.h>

// HorizontalDilation: out[r][c] = max(0, max_{d=-7..7} in[r][c+d]), zero padding.
// Window k=15. Zero padding + final relu => OOB values can be treated as 0.0f.
//
// Round-4 design: row-strip warps + pipelined prefetch (fix latency dilution).
//  - Lane l of a chunk owns cols col0..col0+7 (col0 = C - 8 + 8*l); the +/-7
//    window spans lanes l-1..l+1, resolved with 14 warp shuffles (van Herk).
//  - Each warp processes ROWS_PER_WARP=16 consecutive rows of its chunk,
//    prefetching row r+1's two float4s while computing row r: loads are in
//    flight for the warp's whole lifetime instead of one burst.
//  - Grid = 768 blocks -> fully resident in ONE wave (no launch churn).

#define IMG_W 4096
#define IMG_H 4096
#define OUT_PER_WARP 240
#define WARPS_PER_BLOCK 6
#define THREADS (WARPS_PER_BLOCK * 32)   // 192
#define ROWS_PER_WARP 16

__global__ __launch_bounds__(THREADS)
void HorizontalDilation_kernel(const float* __restrict__ in, float* __restrict__ out) {
    const unsigned FULL = 0xffffffffu;
    const int lane  = threadIdx.x & 31;
    const int warp  = threadIdx.x >> 5;
    const int chunk = blockIdx.x * WARPS_PER_BLOCK + warp;      // 0..17
    const int row0  = blockIdx.y * ROWS_PER_WARP;
    const int C     = chunk * OUT_PER_WARP;
    const int col0  = C - 8 + 8 * lane;                         // lane's 8-col group

    // Groups are 8-aligned; IMG_W % 8 == 0 -> group fully in or fully out.
    const bool inb = (col0 >= 0) & (col0 < IMG_W);
    const bool wr  = inb & (lane >= 1) & (lane <= 30);

    const float* __restrict__ p = in  + (size_t)row0 * IMG_W + col0;
    float*       __restrict__ q = out + (size_t)row0 * IMG_W + col0;

    float4 a, b, na, nb;
    na = nb = make_float4(0.f, 0.f, 0.f, 0.f);

    // Preload row 0.
    if (inb) { a = *(const float4*)p; b = *(const float4*)(p + 4); }
    else     { a = make_float4(0.f,0.f,0.f,0.f); b = make_float4(0.f,0.f,0.f,0.f); }

    #pragma unroll 2
    for (int r = 0; r < ROWS_PER_WARP; r++) {
        // Prefetch next row before computing the current one.
        if (r + 1 < ROWS_PER_WARP) {
            if (inb) {
                const float* pn = p + (size_t)(r + 1) * IMG_W;
                na = *(const float4*)pn;
                nb = *(const float4*)(pn + 4);
            }
        }

        // ---- compute on (a, b): v0..v7 = a.x a.y a.z a.w b.x b.y b.z b.w ----
        const float suf1 = b.w;
        const float suf2 = fmaxf(b.z, suf1);
        const float suf3 = fmaxf(b.y, suf2);
        const float suf4 = fmaxf(b.x, suf3);
        const float suf5 = fmaxf(a.w, suf4);
        const float suf6 = fmaxf(a.z, suf5);
        const float suf7 = fmaxf(a.y, suf6);
        const float m8   = fmaxf(a.x, suf7);
        const float pre1 = a.x;
        const float pre2 = fmaxf(pre1, a.y);
        const float pre3 = fmaxf(pre2, a.z);
        const float pre4 = fmaxf(pre3, a.w);
        const float pre5 = fmaxf(pre4, b.x);
        const float pre6 = fmaxf(pre5, b.y);
        const float pre7 = fmaxf(pre6, b.z);

        const float sU1 = __shfl_up_sync(FULL, suf1, 1);
        const float sU2 = __shfl_up_sync(FULL, suf2, 1);
        const float sU3 = __shfl_up_sync(FULL, suf3, 1);
        const float sU4 = __shfl_up_sync(FULL, suf4, 1);
        const float sU5 = __shfl_up_sync(FULL, suf5, 1);
        const float sU6 = __shfl_up_sync(FULL, suf6, 1);
        const float sU7 = __shfl_up_sync(FULL, suf7, 1);
        const float pD1 = __shfl_down_sync(FULL, pre1, 1);
        const float pD2 = __shfl_down_sync(FULL, pre2, 1);
        const float pD3 = __shfl_down_sync(FULL, pre3, 1);
        const float pD4 = __shfl_down_sync(FULL, pre4, 1);
        const float pD5 = __shfl_down_sync(FULL, pre5, 1);
        const float pD6 = __shfl_down_sync(FULL, pre6, 1);
        const float pD7 = __shfl_down_sync(FULL, pre7, 1);

        // out[j] window [col0+j-7, col0+j+7] = suf_{7-j}[l-1] | m8 | pre_j[l+1]
        const float m8r = fmaxf(m8, 0.f);
        float4 oa, ob;
        oa.x = fmaxf(m8r, sU7);
        oa.y = fmaxf(fmaxf(m8r, sU6), pD1);
        oa.z = fmaxf(fmaxf(m8r, sU5), pD2);
        oa.w = fmaxf(fmaxf(m8r, sU4), pD3);
        ob.x = fmaxf(fmaxf(m8r, sU3), pD4);
        ob.y = fmaxf(fmaxf(m8r, sU2), pD5);
        ob.z = fmaxf(fmaxf(m8r, sU1), pD6);
        ob.w = fmaxf(m8r, pD7);

        if (wr) {
            float* qo = q + (size_t)r * IMG_W;
            __stcs((float4*)qo, oa);
            __stcs((float4*)(qo + 4), ob);
        }

        a = na; b = nb;
    }
}

extern "C" void kernel_launch(void* const* d_in, const int* in_sizes, int n_in,
                              void* d_out, int out_size) {
    const float* img = (const float*)d_in[0];
    float* outp = (float*)d_out;
    (void)in_sizes; (void)n_in; (void)out_size;

    // 18 chunks/row-strip = 3 blocks x 6 warps; 4096/16 = 256 row strips.
    dim3 grid(3, IMG_H / ROWS_PER_WARP);   // (3, 256) = 768 blocks
    dim3 block(THREADS);
    HorizontalDilation_kernel<<<grid, block>>>(img, outp);
}